// round 8
// baseline (speedup 1.0000x reference)
#include <cuda_runtime.h>
#include <cstdint>

// ProbMask: out[b,h,u,col] = (col > m_top[b,h,u]) ? 1.0f : 0.0f  (float32).
// rows = 32768, L_K = 4096 fp32 -> 512 MB of stores. Pure write-bandwidth.
//
// R5: STG path capped by L1tex (84.8%) at 3.8 TB/s.
// R6: TMA bulk stores bypassed L1tex -> 6.06 TB/s, 81 us, DRAM=76%.
// R7: amortize the 32 KB zeros/ones SMEM init over 128 rows/CTA (16x less init
// traffic than R6) and parallelize TMA issue: bulk-async groups are per-thread,
// so each of the 128 threads handles ONE row end-to-end (zeros-prefix copy,
// boundary float4 STG patch, ones-suffix copy) with its own commit/wait.
// 256 CTAs total; per-SM async queues are deep from the first cycle.

static constexpr int L_K          = 4096;
static constexpr int ROW_BYTES    = L_K * 4;      // 16384
static constexpr int ROW_CHUNKS   = L_K / 4;      // 1024 float4 chunks per row
static constexpr int THREADS      = 128;          // one row per thread

__global__ __launch_bounds__(THREADS)
void probmask_tma_kernel(const int* __restrict__ m_top, float* __restrict__ out) {
    __shared__ __align__(16) float zbuf[L_K];     // 16 KB of 0.0f
    __shared__ __align__(16) float obuf[L_K];     // 16 KB of 1.0f

    const int t = threadIdx.x;
    #pragma unroll 4
    for (int i = t; i < L_K; i += THREADS) { zbuf[i] = 0.f; obuf[i] = 1.f; }
    __syncthreads();
    // order generic-proxy SMEM writes before async-proxy (TMA) reads
    asm volatile("fence.proxy.async.shared::cta;" ::: "memory");
    __syncthreads();

    const int row = blockIdx.x * THREADS + t;     // this thread's row
    const int m   = __ldg(&m_top[row]);
    const int zb  = m + 1;                        // leading zero floats, in [1, 4096]

    char* gdst = reinterpret_cast<char*>(out) + static_cast<size_t>(row) * ROW_BYTES;

    // Boundary patch: the single mixed float4 (bytes disjoint from both copies).
    if (zb & 3) {
        const int cb = zb >> 2;                   // mixed chunk's float4 index
        const int c0 = cb << 2;
        float4 v;
        v.x = (c0 + 0 > m) ? 1.f : 0.f;
        v.y = (c0 + 1 > m) ? 1.f : 0.f;
        v.z = (c0 + 2 > m) ? 1.f : 0.f;
        v.w = (c0 + 3 > m) ? 1.f : 0.f;
        reinterpret_cast<float4*>(gdst)[cb] = v;
    }

    const int zchunks = zb >> 2;                          // full zero float4s
    const int ostart  = zchunks + ((zb & 3) ? 1 : 0);     // first all-ones float4
    const uint32_t zbytes = static_cast<uint32_t>(zchunks) * 16u;
    const uint32_t obytes = static_cast<uint32_t>(ROW_CHUNKS - ostart) * 16u;

    const uint32_t zsrc = static_cast<uint32_t>(__cvta_generic_to_shared(zbuf));
    const uint32_t osrc = static_cast<uint32_t>(__cvta_generic_to_shared(obuf));

    if (zbytes)
        asm volatile("cp.async.bulk.global.shared::cta.bulk_group [%0], [%1], %2;"
                     :: "l"(gdst), "r"(zsrc), "r"(zbytes) : "memory");
    if (obytes)
        asm volatile("cp.async.bulk.global.shared::cta.bulk_group [%0], [%1], %2;"
                     :: "l"(gdst + static_cast<size_t>(ostart) * 16), "r"(osrc), "r"(obytes)
                     : "memory");

    asm volatile("cp.async.bulk.commit_group;" ::: "memory");
    // each thread waits for its own copies; CTA SMEM stays alive until all
    // threads (hence all outstanding bulk reads of zbuf/obuf) are done
    asm volatile("cp.async.bulk.wait_group 0;" ::: "memory");
}

extern "C" void kernel_launch(void* const* d_in, const int* in_sizes, int n_in,
                              void* d_out, int out_size) {
    const int rows = out_size / L_K;              // 32768

    // m_top: the int32 input with exactly `rows` elements (metadata: d_in[1]).
    const int* m_top = reinterpret_cast<const int*>(d_in[1]);
    for (int i = 0; i < n_in; i++) {
        if (in_sizes[i] == rows) { m_top = reinterpret_cast<const int*>(d_in[i]); break; }
    }

    float* out = reinterpret_cast<float*>(d_out);
    probmask_tma_kernel<<<rows / THREADS, THREADS>>>(m_top, out);
}